// round 11
// baseline (speedup 1.0000x reference)
#include <cuda_runtime.h>

#define B_    4
#define T_    2048
#define EMB_  2048
#define HD_   128
#define HALF_ 64
#define MTOT  (B_*T_)   // 8192

// Scratch for projected Q/K/V (post-RoPE, tf32-rounded; Q pre-scaled). 4 MB each.
__device__ float g_Q[MTOT*HD_];
__device__ float g_K[MTOT*HD_];
__device__ float g_V[MTOT*HD_];

// ---------------- tf32 mma helpers ----------------
__device__ __forceinline__ float cvt1_tf32(float v) {
    asm("cvt.rna.tf32.f32 %0, %0;" : "+f"(v));
    return v;
}
__device__ __forceinline__ float4 cvt_tf32_4(float4 v) {
    asm("cvt.rna.tf32.f32 %0, %0;\n\t"
        "cvt.rna.tf32.f32 %1, %1;\n\t"
        "cvt.rna.tf32.f32 %2, %2;\n\t"
        "cvt.rna.tf32.f32 %3, %3;"
        : "+f"(v.x), "+f"(v.y), "+f"(v.z), "+f"(v.w));
    return v;
}
__device__ __forceinline__ void mma_tf32(float c[4], const unsigned a[4],
                                         const unsigned b[2]) {
    asm("mma.sync.aligned.m16n8k8.row.col.f32.tf32.tf32.f32 "
        "{%0,%1,%2,%3},{%4,%5,%6,%7},{%8,%9},{%0,%1,%2,%3};"
        : "+f"(c[0]), "+f"(c[1]), "+f"(c[2]), "+f"(c[3])
        : "r"(a[0]), "r"(a[1]), "r"(a[2]), "r"(a[3]),
          "r"(b[0]), "r"(b[1]));
}
// ldmatrix x4: 4 8x4-fp32 blocks; reg i = matrix i, lanes 8i..8i+7 give rows.
__device__ __forceinline__ void ldsm_x4(unsigned& r0, unsigned& r1,
                                        unsigned& r2, unsigned& r3,
                                        unsigned addr) {
    asm volatile("ldmatrix.sync.aligned.m8n8.x4.shared.b16 {%0,%1,%2,%3}, [%4];"
                 : "=r"(r0), "=r"(r1), "=r"(r2), "=r"(r3) : "r"(addr));
}

// ---------------- cp.async helpers ----------------
__device__ __forceinline__ unsigned smem_u32(const void* p) {
    return (unsigned)__cvta_generic_to_shared(p);
}
__device__ __forceinline__ void cp16(unsigned dst, const void* src) {
    asm volatile("cp.async.ca.shared.global [%0], [%1], 16;"
                 :: "r"(dst), "l"(src));
}
__device__ __forceinline__ void cp_commit() {
    asm volatile("cp.async.commit_group;");
}
__device__ __forceinline__ void cp_wait1() {
    asm volatile("cp.async.wait_group 1;");
}

// ---------------------------------------------------------------------------
// Kernel 1: fused QKV projection + RoPE via tf32 mma. (unchanged from R10)
// ---------------------------------------------------------------------------
#define QBM 64
#define QBK 32

struct __align__(16) QkvSmem {
    float A[2][QBM][QBK+4];   // 64 x 36
    float B[2][QBK][132];     // 32 x 132
};

__global__ __launch_bounds__(256) void qkv_kernel(
    const float* __restrict__ x, const float* __restrict__ Wq,
    const float* __restrict__ Wk, const float* __restrict__ Wv,
    const float* __restrict__ rc, const float* __restrict__ rs)
{
    extern __shared__ char smem_raw[];
    QkvSmem& sm = *reinterpret_cast<QkvSmem*>(smem_raw);

    const int which = blockIdx.y;
    const float* __restrict__ W   = (which==0) ? Wq : ((which==1) ? Wk : Wv);
    float*       __restrict__ dst = (which==0) ? g_Q : ((which==1) ? g_K : g_V);

    const int m0   = blockIdx.x * QBM;
    const int tid  = threadIdx.x;
    const int lane = tid & 31;
    const int wid  = tid >> 5;
    const int wm   = wid & 1;
    const int wn   = wid >> 1;
    const int g    = lane >> 2;
    const int tg   = lane & 3;

    const int arow = (lane & 7) + ((lane >> 3) & 1) * 8;
    const int acol = (lane >> 4) * 4;
    const unsigned aBase  = smem_u32(&sm.A[0][wm*32 + arow][acol]);
    const unsigned ABUF   = (unsigned)sizeof(sm.A[0]);
    const unsigned AMF1   = 16u * (QBK+4) * 4u;

    const int ar  = tid >> 3;
    const int ac4 = tid & 7;
    const float* xp = x + (size_t)(m0 + ar)*EMB_ + ac4*4;
    const int br  = wid;
    const int bc4 = lane;
    const float* wp = W + (size_t)br*HD_ + bc4*4;

    {
        float4 a0 = cvt_tf32_4(*(const float4*)(xp));
        float4 a1 = cvt_tf32_4(*(const float4*)(xp + (size_t)32*EMB_));
        *(float4*)&sm.A[0][ar   ][ac4*4] = a0;
        *(float4*)&sm.A[0][ar+32][ac4*4] = a1;
        #pragma unroll
        for (int i = 0; i < 4; i++) {
            float4 bv = cvt_tf32_4(*(const float4*)(wp + (size_t)i*8*HD_));
            *(float4*)&sm.B[0][br + i*8][bc4*4] = bv;
        }
    }
    __syncthreads();

    float acc[2][4][4];
    #pragma unroll
    for (int mf = 0; mf < 2; mf++)
        #pragma unroll
        for (int nf = 0; nf < 4; nf++)
            #pragma unroll
            for (int r = 0; r < 4; r++) acc[mf][nf][r] = 0.f;

    const int NTILES = EMB_ / QBK;   // 64
    for (int t = 0; t < NTILES; ++t) {
        const int cur = t & 1;
        const bool pre = (t + 1 < NTILES);
        float4 na0, na1, nb[4];
        if (pre) {
            const float* xq = xp + (t+1)*QBK;
            const float* wq = wp + (size_t)(t+1)*QBK*HD_;
            na0 = cvt_tf32_4(*(const float4*)(xq));
            na1 = cvt_tf32_4(*(const float4*)(xq + (size_t)32*EMB_));
            #pragma unroll
            for (int i = 0; i < 4; i++)
                nb[i] = cvt_tf32_4(*(const float4*)(wq + (size_t)i*8*HD_));
        }

        const unsigned aAddr = aBase + (unsigned)cur * ABUF;
        const float (*Bs)[132] = sm.B[cur];
        #pragma unroll
        for (int ks = 0; ks < 4; ++ks) {
            const int k0 = ks*8;
            unsigned a0[4], a1[4], b[4][2];
            ldsm_x4(a0[0], a0[1], a0[2], a0[3], aAddr + ks*32);
            ldsm_x4(a1[0], a1[1], a1[2], a1[3], aAddr + AMF1 + ks*32);
            #pragma unroll
            for (int nf = 0; nf < 4; nf++) {
                const int n = wn*32 + nf*8 + g;
                b[nf][0] = __float_as_uint(Bs[k0+tg  ][n]);
                b[nf][1] = __float_as_uint(Bs[k0+tg+4][n]);
            }
            #pragma unroll
            for (int nf = 0; nf < 4; nf++) {
                mma_tf32(acc[0][nf], a0, b[nf]);
                mma_tf32(acc[1][nf], a1, b[nf]);
            }
        }

        if (pre) {
            const int nbuf = 1 - cur;
            *(float4*)&sm.A[nbuf][ar   ][ac4*4] = na0;
            *(float4*)&sm.A[nbuf][ar+32][ac4*4] = na1;
            #pragma unroll
            for (int i = 0; i < 4; i++)
                *(float4*)&sm.B[nbuf][br + i*8][bc4*4] = nb[i];
        }
        __syncthreads();
    }

    const float qscale = 0.088388347648318447f;  // 1/sqrt(128)
    #pragma unroll
    for (int mf = 0; mf < 2; mf++) {
        const int row0 = m0 + wm*32 + mf*16 + g;
        const int row1 = row0 + 8;
        const int t0 = row0 & (T_ - 1);
        const int t1 = row1 & (T_ - 1);
        #pragma unroll
        for (int nf = 0; nf < 4; nf++) {
            const int col = wn*32 + nf*8 + 2*tg;
            const int hi  = col >> 1;
            float re0 = acc[mf][nf][0], im0 = acc[mf][nf][1];
            float re1 = acc[mf][nf][2], im1 = acc[mf][nf][3];
            if (which < 2) {
                float c0 = rc[t0*HALF_ + hi], s0 = rs[t0*HALF_ + hi];
                float c1 = rc[t1*HALF_ + hi], s1 = rs[t1*HALF_ + hi];
                float r2, i2;
                r2 = re0*c0 - im0*s0; i2 = re0*s0 + im0*c0; re0 = r2; im0 = i2;
                r2 = re1*c1 - im1*s1; i2 = re1*s1 + im1*c1; re1 = r2; im1 = i2;
            }
            if (which == 0) { re0 *= qscale; im0 *= qscale; re1 *= qscale; im1 *= qscale; }
            re0 = cvt1_tf32(re0); im0 = cvt1_tf32(im0);
            re1 = cvt1_tf32(re1); im1 = cvt1_tf32(im1);
            *(float2*)&dst[(size_t)row0*HD_ + col] = make_float2(re0, im0);
            *(float2*)&dst[(size_t)row1*HD_ + col] = make_float2(re1, im1);
        }
    }
}

// ---------------------------------------------------------------------------
// Kernel 2: causal flash attention, tf32 mma, DOUBLE-BUFFERED K/V.
// BQ=32, BK=32, 8 warps. Loads for kt+1 issued at top of iter kt; wait depth 1.
// S-phase split into two 8-deep mma chains. 2 blocks/SM (smem ~90KB).
// ---------------------------------------------------------------------------
#define BQ 32
#define BK 32

struct __align__(16) AttnSmem {
    float Q[BQ][132];
    float K[2][BK][132];
    float V[2][BK][136];
    float S[BQ][36];
    float mrow[BQ];
    float lrow[BQ];
    float crow[BQ];
};

__global__ __launch_bounds__(256, 2) void attn_kernel(float* __restrict__ out)
{
    extern __shared__ char smem_raw[];
    AttnSmem& sm = *reinterpret_cast<AttnSmem*>(smem_raw);

    // balanced bid -> (qt, b): pairs heavy with light on same SM residue
    const int bid = blockIdx.x;
    int qt, b;
    if (bid < 108)      { qt = bid >> 2;              b = bid & 3; }
    else if (bid < 148) { int j = bid - 108; qt = 27 + (j >> 2); b = j & 3; }
    else                { int j = bid - 148; qt = 63 - (j >> 2); b = j & 3; }

    const int q0   = qt * BQ;
    const int tid  = threadIdx.x;
    const int lane = tid & 31;
    const int wid  = tid >> 5;
    const int g    = lane >> 2;
    const int tg   = lane & 3;
    const int wm   = wid & 1;
    const int wn   = wid >> 1;

    const float* __restrict__ Qg = g_Q + (size_t)(b*T_)*HD_;
    const float* __restrict__ Kg = g_K + (size_t)(b*T_)*HD_;
    const float* __restrict__ Vg = g_V + (size_t)(b*T_)*HD_;

    // ldmatrix lane address pieces
    const int arow = (lane & 7) + ((lane >> 3) & 1) * 8;
    const int acol = (lane >> 4) * 4;
    const unsigned qAddr = smem_u32(&sm.Q[wm*16 + arow][acol]);
    const unsigned pAddr = smem_u32(&sm.S[wm*16 + arow][acol]);
    const unsigned kAddr0 = smem_u32(&sm.K[0][wn*8 + (lane & 7)][(lane >> 3) * 4]);
    const unsigned KBUF   = (unsigned)sizeof(sm.K[0]);   // 16896 B

    // loader indices
    const int lr  = tid >> 3;          // 0..31
    const int lcf = (tid & 7) * 16;    // float col 0..112

    const int nk = qt + 1;

    // prologue: Q + K0 + V0 as one group (G0)
    {
        const float* srcq = Qg + (size_t)(q0 + lr)*HD_ + lcf;
        unsigned dq = smem_u32(&sm.Q[lr][lcf]);
        #pragma unroll
        for (int i = 0; i < 4; i++) cp16(dq + i*16, srcq + i*4);
        const float* srck = Kg + (size_t)lr*HD_ + lcf;
        const float* srcv = Vg + (size_t)lr*HD_ + lcf;
        unsigned dk = smem_u32(&sm.K[0][lr][lcf]);
        unsigned dv = smem_u32(&sm.V[0][lr][lcf]);
        #pragma unroll
        for (int i = 0; i < 4; i++) cp16(dk + i*16, srck + i*4);
        #pragma unroll
        for (int i = 0; i < 4; i++) cp16(dv + i*16, srcv + i*4);
        cp_commit();
    }
    if (tid < BQ) { sm.mrow[tid] = -1e30f; sm.lrow[tid] = 0.f; }

    float O[4][4];
    #pragma unroll
    for (int nf = 0; nf < 4; nf++)
        #pragma unroll
        for (int r = 0; r < 4; r++) O[nf][r] = 0.f;

    for (int kt = 0; kt < nk; ++kt) {
        const int cur = kt & 1;
        const int k0  = kt * BK;

        // issue loads for kt+1 into the idle buffer (read last at iter kt-1,
        // which ended with a barrier) — then commit; keep 1 group in flight.
        if (kt + 1 < nk) {
            const int nb = 1 - cur;
            const float* srck = Kg + (size_t)(k0 + BK + lr)*HD_ + lcf;
            const float* srcv = Vg + (size_t)(k0 + BK + lr)*HD_ + lcf;
            unsigned dk = smem_u32(&sm.K[nb][lr][lcf]);
            unsigned dv = smem_u32(&sm.V[nb][lr][lcf]);
            #pragma unroll
            for (int i = 0; i < 4; i++) cp16(dk + i*16, srck + i*4);
            #pragma unroll
            for (int i = 0; i < 4; i++) cp16(dv + i*16, srcv + i*4);
        }
        cp_commit();
        cp_wait1();        // group for kt complete (and Q on kt==0)
        __syncthreads();

        // ---- S = Q K^T (ldmatrix A+B, two 8-deep chains) ----
        {
            float sa[4] = {0.f, 0.f, 0.f, 0.f};
            float sb[4] = {0.f, 0.f, 0.f, 0.f};
            const unsigned kAddr = kAddr0 + (unsigned)cur * KBUF;
            #pragma unroll
            for (int kp = 0; kp < 4; kp++) {
                unsigned bb[4], a[4], a2[4];
                ldsm_x4(bb[0], bb[1], bb[2], bb[3], kAddr + kp*64);
                ldsm_x4(a[0], a[1], a[2], a[3], qAddr + kp*64);
                mma_tf32(sa, a, &bb[0]);
                ldsm_x4(a2[0], a2[1], a2[2], a2[3], qAddr + kp*64 + 32);
                mma_tf32(sb, a2, &bb[2]);
            }
            #pragma unroll
            for (int kp = 4; kp < 8; kp++) {
                unsigned bb[4], a[4], a2[4];
                ldsm_x4(bb[0], bb[1], bb[2], bb[3], kAddr + kp*64);
                ldsm_x4(a[0], a[1], a[2], a[3], qAddr + kp*64);
                mma_tf32(sa, a, &bb[0]);
                ldsm_x4(a2[0], a2[1], a2[2], a2[3], qAddr + kp*64 + 32);
                mma_tf32(sb, a2, &bb[2]);
            }
            const int ar0 = wm*16 + g;
            const int qg0 = q0 + ar0, qg1 = qg0 + 8;
            const int c   = wn*8 + 2*tg;
            const int kg  = k0 + c;
            sm.S[ar0  ][c  ] = (kg   <= qg0) ? sa[0]+sb[0] : -1e9f;
            sm.S[ar0  ][c+1] = (kg+1 <= qg0) ? sa[1]+sb[1] : -1e9f;
            sm.S[ar0+8][c  ] = (kg   <= qg1) ? sa[2]+sb[2] : -1e9f;
            sm.S[ar0+8][c+1] = (kg+1 <= qg1) ? sa[3]+sb[3] : -1e9f;
        }
        __syncthreads();

        // ---- online softmax: 32 rows x 8 lanes ----
        {
            const int r = tid >> 3, sub = tid & 7;
            float4 sv = *(const float4*)&sm.S[r][sub*4];
            float mold = sm.mrow[r];
            float mx = fmaxf(fmaxf(sv.x, sv.y), fmaxf(sv.z, sv.w));
            mx = fmaxf(mx, mold);
            #pragma unroll
            for (int o = 1; o < 8; o <<= 1)
                mx = fmaxf(mx, __shfl_xor_sync(0xffffffffu, mx, o));
            float e0 = __expf(sv.x - mx), e1 = __expf(sv.y - mx);
            float e2 = __expf(sv.z - mx), e3 = __expf(sv.w - mx);
            float sum = (e0+e1) + (e2+e3);
            #pragma unroll
            for (int o = 1; o < 8; o <<= 1)
                sum += __shfl_xor_sync(0xffffffffu, sum, o);
            *(float4*)&sm.S[r][sub*4] =
                make_float4(cvt1_tf32(e0), cvt1_tf32(e1),
                            cvt1_tf32(e2), cvt1_tf32(e3));
            if (sub == 0) {
                float corr = __expf(mold - mx);
                sm.crow[r] = corr;
                sm.mrow[r] = mx;
                sm.lrow[r] = sm.lrow[r]*corr + sum;
            }
        }
        __syncthreads();

        // ---- O = O*corr + P V (ldmatrix A, scalar conflict-free B) ----
        {
            const int r0 = wm*16 + g;
            const float cf0 = sm.crow[r0];
            const float cf1 = sm.crow[r0 + 8];
            const float (*Vs)[136] = sm.V[cur];
            #pragma unroll
            for (int nf = 0; nf < 4; nf++) {
                O[nf][0] *= cf0; O[nf][1] *= cf0;
                O[nf][2] *= cf1; O[nf][3] *= cf1;
            }
            #pragma unroll
            for (int ks = 0; ks < 4; ks++) {
                const int kk = ks*8;
                unsigned a[4];
                ldsm_x4(a[0], a[1], a[2], a[3], pAddr + ks*32);
                #pragma unroll
                for (int nf = 0; nf < 4; nf++) {
                    const int n = wn*32 + nf*8 + g;
                    unsigned bb[2];
                    bb[0] = __float_as_uint(Vs[kk+tg  ][n]);
                    bb[1] = __float_as_uint(Vs[kk+tg+4][n]);
                    mma_tf32(O[nf], a, bb);
                }
            }
        }
        __syncthreads();   // V[cur]/S consumed: safe for kt+1's S write and
                           // kt+2's load issue into buf cur
    }

    // ---- final normalize + store ----
    {
        const int r0 = wm*16 + g;
        const float inv0 = 1.0f / sm.lrow[r0];
        const float inv1 = 1.0f / sm.lrow[r0 + 8];
        const size_t ro0 = (size_t)(b*T_ + q0 + r0)*HD_;
        const size_t ro1 = ro0 + (size_t)8*HD_;
        #pragma unroll
        for (int nf = 0; nf < 4; nf++) {
            const int col = wn*32 + nf*8 + 2*tg;
            *(float2*)&out[ro0 + col] = make_float2(O[nf][0]*inv0, O[nf][1]*inv0);
            *(float2*)&out[ro1 + col] = make_float2(O[nf][2]*inv1, O[nf][3]*inv1);
        }
    }
}

// ---------------------------------------------------------------------------
extern "C" void kernel_launch(void* const* d_in, const int* in_sizes, int n_in,
                              void* d_out, int out_size)
{
    const float* x  = (const float*)d_in[0];
    const float* Wq = (const float*)d_in[1];
    const float* Wk = (const float*)d_in[2];
    const float* Wv = (const float*)d_in[3];
    const float* rc = (const float*)d_in[4];
    const float* rs = (const float*)d_in[5];
    // d_in[6] (mask) is exactly the causal -1e9 mask; computed analytically.
    float* out = (float*)d_out;

    cudaFuncSetAttribute(qkv_kernel,
                         cudaFuncAttributeMaxDynamicSharedMemorySize,
                         (int)sizeof(QkvSmem));
    cudaFuncSetAttribute(attn_kernel,
                         cudaFuncAttributeMaxDynamicSharedMemorySize,
                         (int)sizeof(AttnSmem));

    dim3 g1(MTOT/QBM, 3);
    qkv_kernel<<<g1, 256, sizeof(QkvSmem)>>>(x, Wq, Wk, Wv, rc, rs);

    attn_kernel<<<256, 256, sizeof(AttnSmem)>>>(out);
}

// round 15
// speedup vs baseline: 1.2017x; 1.2017x over previous
#include <cuda_runtime.h>

#define B_    4
#define T_    2048
#define EMB_  2048
#define HD_   128
#define HALF_ 64
#define MTOT  (B_*T_)   // 8192

// Scratch for projected Q/K/V (post-RoPE, tf32-rounded; Q pre-scaled). 4 MB each.
__device__ float g_Q[MTOT*HD_];
__device__ float g_K[MTOT*HD_];
__device__ float g_V[MTOT*HD_];

// ---------------- tf32 mma helpers ----------------
__device__ __forceinline__ float cvt1_tf32(float v) {
    asm("cvt.rna.tf32.f32 %0, %0;" : "+f"(v));
    return v;
}
__device__ __forceinline__ float4 cvt_tf32_4(float4 v) {
    asm("cvt.rna.tf32.f32 %0, %0;\n\t"
        "cvt.rna.tf32.f32 %1, %1;\n\t"
        "cvt.rna.tf32.f32 %2, %2;\n\t"
        "cvt.rna.tf32.f32 %3, %3;"
        : "+f"(v.x), "+f"(v.y), "+f"(v.z), "+f"(v.w));
    return v;
}
__device__ __forceinline__ void mma_tf32(float c[4], const unsigned a[4],
                                         const unsigned b[2]) {
    asm("mma.sync.aligned.m16n8k8.row.col.f32.tf32.tf32.f32 "
        "{%0,%1,%2,%3},{%4,%5,%6,%7},{%8,%9},{%0,%1,%2,%3};"
        : "+f"(c[0]), "+f"(c[1]), "+f"(c[2]), "+f"(c[3])
        : "r"(a[0]), "r"(a[1]), "r"(a[2]), "r"(a[3]),
          "r"(b[0]), "r"(b[1]));
}
// ldmatrix x4: 4 8x4-fp32 blocks; reg i = matrix i, lanes 8i..8i+7 give rows.
__device__ __forceinline__ void ldsm_x4(unsigned& r0, unsigned& r1,
                                        unsigned& r2, unsigned& r3,
                                        unsigned addr) {
    asm volatile("ldmatrix.sync.aligned.m8n8.x4.shared.b16 {%0,%1,%2,%3}, [%4];"
                 : "=r"(r0), "=r"(r1), "=r"(r2), "=r"(r3) : "r"(addr));
}

// ---------------- cp.async helpers ----------------
__device__ __forceinline__ unsigned smem_u32(const void* p) {
    return (unsigned)__cvta_generic_to_shared(p);
}
__device__ __forceinline__ void cp16(unsigned dst, const void* src) {
    asm volatile("cp.async.ca.shared.global [%0], [%1], 16;"
                 :: "r"(dst), "l"(src));
}
__device__ __forceinline__ void cp_commit() {
    asm volatile("cp.async.commit_group;");
}
__device__ __forceinline__ void cp_wait0() {
    asm volatile("cp.async.wait_group 0;");
}

// ---------------------------------------------------------------------------
// Kernel 1: fused QKV projection + RoPE via tf32 mma. (unchanged from R10)
// ---------------------------------------------------------------------------
#define QBM 64
#define QBK 32

struct __align__(16) QkvSmem {
    float A[2][QBM][QBK+4];   // 64 x 36
    float B[2][QBK][132];     // 32 x 132
};

__global__ __launch_bounds__(256) void qkv_kernel(
    const float* __restrict__ x, const float* __restrict__ Wq,
    const float* __restrict__ Wk, const float* __restrict__ Wv,
    const float* __restrict__ rc, const float* __restrict__ rs)
{
    extern __shared__ char smem_raw[];
    QkvSmem& sm = *reinterpret_cast<QkvSmem*>(smem_raw);

    const int which = blockIdx.y;
    const float* __restrict__ W   = (which==0) ? Wq : ((which==1) ? Wk : Wv);
    float*       __restrict__ dst = (which==0) ? g_Q : ((which==1) ? g_K : g_V);

    const int m0   = blockIdx.x * QBM;
    const int tid  = threadIdx.x;
    const int lane = tid & 31;
    const int wid  = tid >> 5;
    const int wm   = wid & 1;
    const int wn   = wid >> 1;
    const int g    = lane >> 2;
    const int tg   = lane & 3;

    const int arow = (lane & 7) + ((lane >> 3) & 1) * 8;
    const int acol = (lane >> 4) * 4;
    const unsigned aBase  = smem_u32(&sm.A[0][wm*32 + arow][acol]);
    const unsigned ABUF   = (unsigned)sizeof(sm.A[0]);
    const unsigned AMF1   = 16u * (QBK+4) * 4u;

    const int ar  = tid >> 3;
    const int ac4 = tid & 7;
    const float* xp = x + (size_t)(m0 + ar)*EMB_ + ac4*4;
    const int br  = wid;
    const int bc4 = lane;
    const float* wp = W + (size_t)br*HD_ + bc4*4;

    {
        float4 a0 = cvt_tf32_4(*(const float4*)(xp));
        float4 a1 = cvt_tf32_4(*(const float4*)(xp + (size_t)32*EMB_));
        *(float4*)&sm.A[0][ar   ][ac4*4] = a0;
        *(float4*)&sm.A[0][ar+32][ac4*4] = a1;
        #pragma unroll
        for (int i = 0; i < 4; i++) {
            float4 bv = cvt_tf32_4(*(const float4*)(wp + (size_t)i*8*HD_));
            *(float4*)&sm.B[0][br + i*8][bc4*4] = bv;
        }
    }
    __syncthreads();

    float acc[2][4][4];
    #pragma unroll
    for (int mf = 0; mf < 2; mf++)
        #pragma unroll
        for (int nf = 0; nf < 4; nf++)
            #pragma unroll
            for (int r = 0; r < 4; r++) acc[mf][nf][r] = 0.f;

    const int NTILES = EMB_ / QBK;   // 64
    for (int t = 0; t < NTILES; ++t) {
        const int cur = t & 1;
        const bool pre = (t + 1 < NTILES);
        float4 na0, na1, nb[4];
        if (pre) {
            const float* xq = xp + (t+1)*QBK;
            const float* wq = wp + (size_t)(t+1)*QBK*HD_;
            na0 = cvt_tf32_4(*(const float4*)(xq));
            na1 = cvt_tf32_4(*(const float4*)(xq + (size_t)32*EMB_));
            #pragma unroll
            for (int i = 0; i < 4; i++)
                nb[i] = cvt_tf32_4(*(const float4*)(wq + (size_t)i*8*HD_));
        }

        const unsigned aAddr = aBase + (unsigned)cur * ABUF;
        const float (*Bs)[132] = sm.B[cur];
        #pragma unroll
        for (int ks = 0; ks < 4; ++ks) {
            const int k0 = ks*8;
            unsigned a0[4], a1[4], b[4][2];
            ldsm_x4(a0[0], a0[1], a0[2], a0[3], aAddr + ks*32);
            ldsm_x4(a1[0], a1[1], a1[2], a1[3], aAddr + AMF1 + ks*32);
            #pragma unroll
            for (int nf = 0; nf < 4; nf++) {
                const int n = wn*32 + nf*8 + g;
                b[nf][0] = __float_as_uint(Bs[k0+tg  ][n]);
                b[nf][1] = __float_as_uint(Bs[k0+tg+4][n]);
            }
            #pragma unroll
            for (int nf = 0; nf < 4; nf++) {
                mma_tf32(acc[0][nf], a0, b[nf]);
                mma_tf32(acc[1][nf], a1, b[nf]);
            }
        }

        if (pre) {
            const int nbuf = 1 - cur;
            *(float4*)&sm.A[nbuf][ar   ][ac4*4] = na0;
            *(float4*)&sm.A[nbuf][ar+32][ac4*4] = na1;
            #pragma unroll
            for (int i = 0; i < 4; i++)
                *(float4*)&sm.B[nbuf][br + i*8][bc4*4] = nb[i];
        }
        __syncthreads();
    }

    const float qscale = 0.088388347648318447f;  // 1/sqrt(128)
    #pragma unroll
    for (int mf = 0; mf < 2; mf++) {
        const int row0 = m0 + wm*32 + mf*16 + g;
        const int row1 = row0 + 8;
        const int t0 = row0 & (T_ - 1);
        const int t1 = row1 & (T_ - 1);
        #pragma unroll
        for (int nf = 0; nf < 4; nf++) {
            const int col = wn*32 + nf*8 + 2*tg;
            const int hi  = col >> 1;
            float re0 = acc[mf][nf][0], im0 = acc[mf][nf][1];
            float re1 = acc[mf][nf][2], im1 = acc[mf][nf][3];
            if (which < 2) {
                float c0 = rc[t0*HALF_ + hi], s0 = rs[t0*HALF_ + hi];
                float c1 = rc[t1*HALF_ + hi], s1 = rs[t1*HALF_ + hi];
                float r2, i2;
                r2 = re0*c0 - im0*s0; i2 = re0*s0 + im0*c0; re0 = r2; im0 = i2;
                r2 = re1*c1 - im1*s1; i2 = re1*s1 + im1*c1; re1 = r2; im1 = i2;
            }
            if (which == 0) { re0 *= qscale; im0 *= qscale; re1 *= qscale; im1 *= qscale; }
            re0 = cvt1_tf32(re0); im0 = cvt1_tf32(im0);
            re1 = cvt1_tf32(re1); im1 = cvt1_tf32(im1);
            *(float2*)&dst[(size_t)row0*HD_ + col] = make_float2(re0, im0);
            *(float2*)&dst[(size_t)row1*HD_ + col] = make_float2(re1, im1);
        }
    }
}

// ---------------------------------------------------------------------------
// Kernel 2: causal flash attention — warp-owns-rows, register softmax.
// 128 threads (4 warps). Warp w: rows (w&1)*16..+15, O cols (w>>1)*64..+63.
// Each warp computes the FULL S for its 16 rows (row-half pairs recompute S
// redundantly — removes all cross-warp softmax coupling).
// ONE __syncthreads per iteration (K/V double-buffer recycle).
// ---------------------------------------------------------------------------
#define BQ 32
#define BK 32

struct __align__(16) AttnSmem {
    float Q[BQ][132];
    float K[2][BK][132];
    float V[2][BK][136];
    float P[4][16][36];    // per-warp P patches
};

__global__ __launch_bounds__(128, 2) void attn_kernel(float* __restrict__ out)
{
    extern __shared__ char smem_raw[];
    AttnSmem& sm = *reinterpret_cast<AttnSmem*>(smem_raw);

    // balanced bid -> (qt, b): pairs heavy with light on same SM residue
    const int bid = blockIdx.x;
    int qt, b;
    if (bid < 108)      { qt = bid >> 2;              b = bid & 3; }
    else if (bid < 148) { int j = bid - 108; qt = 27 + (j >> 2); b = j & 3; }
    else                { int j = bid - 148; qt = 63 - (j >> 2); b = j & 3; }

    const int q0   = qt * BQ;
    const int tid  = threadIdx.x;
    const int lane = tid & 31;
    const int w    = tid >> 5;
    const int g    = lane >> 2;
    const int tg   = lane & 3;
    const int wrow = (w & 1) * 16;    // row half
    const int wcol = (w >> 1) * 64;   // O col half

    const float* __restrict__ Qg = g_Q + (size_t)(b*T_)*HD_;
    const float* __restrict__ Kg = g_K + (size_t)(b*T_)*HD_;
    const float* __restrict__ Vg = g_V + (size_t)(b*T_)*HD_;

    // ldmatrix lane address pieces
    const int arow = (lane & 7) + ((lane >> 3) & 1) * 8;
    const int acol = (lane >> 4) * 4;
    const unsigned qAddr = smem_u32(&sm.Q[wrow + arow][acol]);
    const unsigned pAddr = smem_u32(&sm.P[w][arow][acol]);
    const unsigned kBase = smem_u32(&sm.K[0][(lane >> 3)*8 + (lane & 7)][0]);
    const unsigned KBUF  = (unsigned)sizeof(sm.K[0]);   // 32*132*4 bytes

    // prologue: Q + K0 + V0 in one cp.async group
    // (each tile = 32 rows x 32 float4s = 1024 cp16 ops; 128 thr x 8 iters)
    {
        #pragma unroll
        for (int i = 0; i < 8; i++) {
            int idx = tid + i*128;
            int r = idx >> 5, c4 = idx & 31;
            cp16(smem_u32(&sm.Q[r][c4*4]), Qg + (size_t)(q0 + r)*HD_ + c4*4);
        }
        #pragma unroll
        for (int i = 0; i < 8; i++) {
            int idx = tid + i*128;
            int r = idx >> 5, c4 = idx & 31;
            cp16(smem_u32(&sm.K[0][r][c4*4]), Kg + (size_t)r*HD_ + c4*4);
            cp16(smem_u32(&sm.V[0][r][c4*4]), Vg + (size_t)r*HD_ + c4*4);
        }
        cp_commit();
        cp_wait0();
        __syncthreads();
    }

    // preload Q fragments (iteration-invariant): 16 A-frags = 64 regs
    unsigned qf[16][4];
    #pragma unroll
    for (int ks = 0; ks < 16; ks++)
        ldsm_x4(qf[ks][0], qf[ks][1], qf[ks][2], qf[ks][3], qAddr + ks*32);

    float O[8][4];
    #pragma unroll
    for (int nf = 0; nf < 8; nf++)
        #pragma unroll
        for (int r = 0; r < 4; r++) O[nf][r] = 0.f;
    float m0 = -1e30f, m1 = -1e30f, l0 = 0.f, l1 = 0.f;

    const int qg0 = q0 + wrow + g, qg1 = qg0 + 8;
    const int nk = qt + 1;

    for (int kt = 0; kt < nk; ++kt) {
        const int cur = kt & 1;
        const int k0  = kt * BK;

        if (kt > 0) {
            cp_wait0();        // group for tile kt arrived (prefetched 1 iter ago)
            __syncthreads();   // all warps done with iter kt-1; cp data visible
        }
        // prefetch K/V for kt+1 into the idle buffer
        if (kt + 1 < nk) {
            const int nb = 1 - cur;
            #pragma unroll
            for (int i = 0; i < 8; i++) {
                int idx = tid + i*128;
                int r = idx >> 5, c4 = idx & 31;
                cp16(smem_u32(&sm.K[nb][r][c4*4]),
                     Kg + (size_t)(k0 + BK + r)*HD_ + c4*4);
                cp16(smem_u32(&sm.V[nb][r][c4*4]),
                     Vg + (size_t)(k0 + BK + r)*HD_ + c4*4);
            }
            cp_commit();
        }

        // ---- S = Q K^T : full 16x32 per warp (8 chains of 8) ----
        float sA[4][4], sB[4][4];
        #pragma unroll
        for (int nf = 0; nf < 4; nf++)
            #pragma unroll
            for (int r = 0; r < 4; r++) { sA[nf][r] = 0.f; sB[nf][r] = 0.f; }
        {
            const unsigned ka = kBase + (unsigned)cur * KBUF;
            #pragma unroll
            for (int ks = 0; ks < 8; ks++) {
                unsigned b0[4], b1[4];
                ldsm_x4(b0[0], b0[1], b0[2], b0[3], ka + ks*32);
                ldsm_x4(b1[0], b1[1], b1[2], b1[3], ka + ks*32 + 16);
                #pragma unroll
                for (int nf = 0; nf < 4; nf++) {
                    unsigned bb[2] = { b0[nf], b1[nf] };
                    mma_tf32(sA[nf], qf[ks], bb);
                }
            }
            #pragma unroll
            for (int ks = 8; ks < 16; ks++) {
                unsigned b0[4], b1[4];
                ldsm_x4(b0[0], b0[1], b0[2], b0[3], ka + ks*32);
                ldsm_x4(b1[0], b1[1], b1[2], b1[3], ka + ks*32 + 16);
                #pragma unroll
                for (int nf = 0; nf < 4; nf++) {
                    unsigned bb[2] = { b0[nf], b1[nf] };
                    mma_tf32(sB[nf], qf[ks], bb);
                }
            }
        }

        // ---- mask + register softmax (quad shuffles only) ----
        float s[4][4];
        #pragma unroll
        for (int nf = 0; nf < 4; nf++) {
            const int col = k0 + nf*8 + 2*tg;
            s[nf][0] = (col   <= qg0) ? sA[nf][0]+sB[nf][0] : -1e9f;
            s[nf][1] = (col+1 <= qg0) ? sA[nf][1]+sB[nf][1] : -1e9f;
            s[nf][2] = (col   <= qg1) ? sA[nf][2]+sB[nf][2] : -1e9f;
            s[nf][3] = (col+1 <= qg1) ? sA[nf][3]+sB[nf][3] : -1e9f;
        }
        float mx0 = fmaxf(fmaxf(s[0][0], s[0][1]), fmaxf(s[1][0], s[1][1]));
        mx0 = fmaxf(mx0, fmaxf(fmaxf(s[2][0], s[2][1]), fmaxf(s[3][0], s[3][1])));
        float mx1 = fmaxf(fmaxf(s[0][2], s[0][3]), fmaxf(s[1][2], s[1][3]));
        mx1 = fmaxf(mx1, fmaxf(fmaxf(s[2][2], s[2][3]), fmaxf(s[3][2], s[3][3])));
        #pragma unroll
        for (int o = 1; o < 4; o <<= 1) {
            mx0 = fmaxf(mx0, __shfl_xor_sync(0xffffffffu, mx0, o));
            mx1 = fmaxf(mx1, __shfl_xor_sync(0xffffffffu, mx1, o));
        }
        const float nm0 = fmaxf(m0, mx0), nm1 = fmaxf(m1, mx1);
        const float corr0 = __expf(m0 - nm0), corr1 = __expf(m1 - nm1);
        m0 = nm0; m1 = nm1;

        float p[4][4];
        float sum0 = 0.f, sum1 = 0.f;
        #pragma unroll
        for (int nf = 0; nf < 4; nf++) {
            p[nf][0] = __expf(s[nf][0] - nm0); sum0 += p[nf][0];
            p[nf][1] = __expf(s[nf][1] - nm0); sum0 += p[nf][1];
            p[nf][2] = __expf(s[nf][2] - nm1); sum1 += p[nf][2];
            p[nf][3] = __expf(s[nf][3] - nm1); sum1 += p[nf][3];
        }
        #pragma unroll
        for (int o = 1; o < 4; o <<= 1) {
            sum0 += __shfl_xor_sync(0xffffffffu, sum0, o);
            sum1 += __shfl_xor_sync(0xffffffffu, sum1, o);
        }
        l0 = l0*corr0 + sum0;
        l1 = l1*corr1 + sum1;

        // ---- P -> warp-private smem patch (tf32), then ldmatrix A-frags ----
        #pragma unroll
        for (int nf = 0; nf < 4; nf++) {
            *(float2*)&sm.P[w][g  ][nf*8 + 2*tg] =
                make_float2(cvt1_tf32(p[nf][0]), cvt1_tf32(p[nf][1]));
            *(float2*)&sm.P[w][g+8][nf*8 + 2*tg] =
                make_float2(cvt1_tf32(p[nf][2]), cvt1_tf32(p[nf][3]));
        }
        __syncwarp();
        unsigned pf[4][4];
        #pragma unroll
        for (int ks = 0; ks < 4; ks++)
            ldsm_x4(pf[ks][0], pf[ks][1], pf[ks][2], pf[ks][3], pAddr + ks*32);

        // ---- O = O*corr + P V ----
        #pragma unroll
        for (int nf = 0; nf < 8; nf++) {
            O[nf][0] *= corr0; O[nf][1] *= corr0;
            O[nf][2] *= corr1; O[nf][3] *= corr1;
        }
        {
            const float (*Vs)[136] = sm.V[cur];
            #pragma unroll
            for (int ks = 0; ks < 4; ks++) {
                const int kk = ks*8;
                #pragma unroll
                for (int nf = 0; nf < 8; nf++) {
                    const int n = wcol + nf*8 + g;
                    unsigned bb[2];
                    bb[0] = __float_as_uint(Vs[kk+tg  ][n]);
                    bb[1] = __float_as_uint(Vs[kk+tg+4][n]);
                    mma_tf32(O[nf], pf[ks], bb);
                }
            }
        }
    }

    // ---- final normalize + store ----
    {
        const float inv0 = 1.0f / l0;
        const float inv1 = 1.0f / l1;
        const size_t ro0 = (size_t)(b*T_ + q0 + wrow + g)*HD_;
        const size_t ro1 = ro0 + (size_t)8*HD_;
        #pragma unroll
        for (int nf = 0; nf < 8; nf++) {
            const int col = wcol + nf*8 + 2*tg;
            *(float2*)&out[ro0 + col] = make_float2(O[nf][0]*inv0, O[nf][1]*inv0);
            *(float2*)&out[ro1 + col] = make_float2(O[nf][2]*inv1, O[nf][3]*inv1);
        }
    }
}

// ---------------------------------------------------------------------------
extern "C" void kernel_launch(void* const* d_in, const int* in_sizes, int n_in,
                              void* d_out, int out_size)
{
    const float* x  = (const float*)d_in[0];
    const float* Wq = (const float*)d_in[1];
    const float* Wk = (const float*)d_in[2];
    const float* Wv = (const float*)d_in[3];
    const float* rc = (const float*)d_in[4];
    const float* rs = (const float*)d_in[5];
    // d_in[6] (mask) is exactly the causal -1e9 mask; computed analytically.
    float* out = (float*)d_out;

    cudaFuncSetAttribute(qkv_kernel,
                         cudaFuncAttributeMaxDynamicSharedMemorySize,
                         (int)sizeof(QkvSmem));
    cudaFuncSetAttribute(attn_kernel,
                         cudaFuncAttributeMaxDynamicSharedMemorySize,
                         (int)sizeof(AttnSmem));

    dim3 g1(MTOT/QBM, 3);
    qkv_kernel<<<g1, 256, sizeof(QkvSmem)>>>(x, Wq, Wk, Wv, rc, rs);

    attn_kernel<<<256, 128, sizeof(AttnSmem)>>>(out);
}

// round 16
// speedup vs baseline: 1.2371x; 1.0294x over previous
#include <cuda_runtime.h>

#define B_    4
#define T_    2048
#define EMB_  2048
#define HD_   128
#define HALF_ 64
#define MTOT  (B_*T_)   // 8192

// Scratch for projected Q/K/V (post-RoPE, tf32-rounded; Q pre-scaled). 4 MB each.
__device__ float g_Q[MTOT*HD_];
__device__ float g_K[MTOT*HD_];
__device__ float g_V[MTOT*HD_];

// ---------------- tf32 mma helpers ----------------
__device__ __forceinline__ float cvt1_tf32(float v) {
    asm("cvt.rna.tf32.f32 %0, %0;" : "+f"(v));
    return v;
}
__device__ __forceinline__ unsigned cvtu_tf32(unsigned u) {
    float f = __uint_as_float(u);
    asm("cvt.rna.tf32.f32 %0, %0;" : "+f"(f));
    return __float_as_uint(f);
}
__device__ __forceinline__ void mma_tf32(float c[4], const unsigned a[4],
                                         const unsigned b[2]) {
    asm("mma.sync.aligned.m16n8k8.row.col.f32.tf32.tf32.f32 "
        "{%0,%1,%2,%3},{%4,%5,%6,%7},{%8,%9},{%0,%1,%2,%3};"
        : "+f"(c[0]), "+f"(c[1]), "+f"(c[2]), "+f"(c[3])
        : "r"(a[0]), "r"(a[1]), "r"(a[2]), "r"(a[3]),
          "r"(b[0]), "r"(b[1]));
}
// ldmatrix x4: 4 8x4-fp32 blocks; reg i = matrix i, lanes 8i..8i+7 give rows.
__device__ __forceinline__ void ldsm_x4(unsigned& r0, unsigned& r1,
                                        unsigned& r2, unsigned& r3,
                                        unsigned addr) {
    asm volatile("ldmatrix.sync.aligned.m8n8.x4.shared.b16 {%0,%1,%2,%3}, [%4];"
                 : "=r"(r0), "=r"(r1), "=r"(r2), "=r"(r3) : "r"(addr));
}

// ---------------- cp.async helpers ----------------
__device__ __forceinline__ unsigned smem_u32(const void* p) {
    return (unsigned)__cvta_generic_to_shared(p);
}
__device__ __forceinline__ void cp16(unsigned dst, const void* src) {
    asm volatile("cp.async.ca.shared.global [%0], [%1], 16;"
                 :: "r"(dst), "l"(src));
}
__device__ __forceinline__ void cp_commit() {
    asm volatile("cp.async.commit_group;");
}
__device__ __forceinline__ void cp_wait0() {
    asm volatile("cp.async.wait_group 0;");
}

// ---------------------------------------------------------------------------
// Kernel 1: fused QKV projection + RoPE via tf32 mma.
// BM=64, BN=128, BK=32, 256 threads, warp tile 32x32.
// cp.async double-buffered loads (raw fp32); RNA tf32 cvt applied in-register
// after ldsm/LDS (numerically identical to pre-store cvt).
// launch_bounds(256,2) -> 2 blocks/SM for latency hiding.
// ---------------------------------------------------------------------------
#define QBM 64
#define QBK 32

struct __align__(16) QkvSmem {
    float A[2][QBM][QBK+4];   // 64 x 36 (raw fp32)
    float B[2][QBK][132];     // 32 x 132 (raw fp32)
};

__global__ __launch_bounds__(256, 2) void qkv_kernel(
    const float* __restrict__ x, const float* __restrict__ Wq,
    const float* __restrict__ Wk, const float* __restrict__ Wv,
    const float* __restrict__ rc, const float* __restrict__ rs)
{
    extern __shared__ char smem_raw[];
    QkvSmem& sm = *reinterpret_cast<QkvSmem*>(smem_raw);

    const int which = blockIdx.y;
    const float* __restrict__ W   = (which==0) ? Wq : ((which==1) ? Wk : Wv);
    float*       __restrict__ dst = (which==0) ? g_Q : ((which==1) ? g_K : g_V);

    const int m0   = blockIdx.x * QBM;
    const int tid  = threadIdx.x;
    const int lane = tid & 31;
    const int wid  = tid >> 5;
    const int wm   = wid & 1;
    const int wn   = wid >> 1;
    const int g    = lane >> 2;
    const int tg   = lane & 3;

    const int arow = (lane & 7) + ((lane >> 3) & 1) * 8;
    const int acol = (lane >> 4) * 4;
    const unsigned aBase  = smem_u32(&sm.A[0][wm*32 + arow][acol]);
    const unsigned ABUF   = (unsigned)sizeof(sm.A[0]);    // 9216 B
    const unsigned AMF1   = 16u * (QBK+4) * 4u;           // +16 rows

    // cp.async loader indices
    const int alr  = tid >> 3;         // 0..31 (A uses idx>>3 over 512 f4)
    const int alc4 = tid & 7;
    const int blr  = tid >> 5;         // B: idx>>5 over 1024 f4
    const int blc4 = tid & 31;

    // prologue: tile 0
    {
        #pragma unroll
        for (int i = 0; i < 2; i++) {
            int idx = tid + i*256;
            int r = idx >> 3, c4 = idx & 7;
            cp16(smem_u32(&sm.A[0][r][c4*4]), x + (size_t)(m0 + r)*EMB_ + c4*4);
        }
        #pragma unroll
        for (int i = 0; i < 4; i++) {
            int idx = tid + i*256;
            int r = idx >> 5, c4 = idx & 31;
            cp16(smem_u32(&sm.B[0][r][c4*4]), W + (size_t)r*HD_ + c4*4);
        }
        cp_commit();
    }
    (void)alr; (void)alc4; (void)blr; (void)blc4;

    float acc[2][4][4];
    #pragma unroll
    for (int mf = 0; mf < 2; mf++)
        #pragma unroll
        for (int nf = 0; nf < 4; nf++)
            #pragma unroll
            for (int r = 0; r < 4; r++) acc[mf][nf][r] = 0.f;

    const int NTILES = EMB_ / QBK;   // 64
    for (int t = 0; t < NTILES; ++t) {
        const int cur = t & 1;

        cp_wait0();          // tile t arrived (committed at t-1)
        __syncthreads();     // all warps done computing tile t-1 (buf 1-cur free)

        // issue loads for tile t+1 into the idle buffer
        if (t + 1 < NTILES) {
            const int nb = 1 - cur;
            const int k0n = (t+1)*QBK;
            #pragma unroll
            for (int i = 0; i < 2; i++) {
                int idx = tid + i*256;
                int r = idx >> 3, c4 = idx & 7;
                cp16(smem_u32(&sm.A[nb][r][c4*4]),
                     x + (size_t)(m0 + r)*EMB_ + k0n + c4*4);
            }
            #pragma unroll
            for (int i = 0; i < 4; i++) {
                int idx = tid + i*256;
                int r = idx >> 5, c4 = idx & 31;
                cp16(smem_u32(&sm.B[nb][r][c4*4]),
                     W + (size_t)(k0n + r)*HD_ + c4*4);
            }
            cp_commit();
        }

        const unsigned aAddr = aBase + (unsigned)cur * ABUF;
        const float (*Bs)[132] = sm.B[cur];
        #pragma unroll
        for (int ks = 0; ks < 4; ++ks) {
            const int k0 = ks*8;
            unsigned a0[4], a1[4], b[4][2];
            ldsm_x4(a0[0], a0[1], a0[2], a0[3], aAddr + ks*32);
            ldsm_x4(a1[0], a1[1], a1[2], a1[3], aAddr + AMF1 + ks*32);
            #pragma unroll
            for (int i = 0; i < 4; i++) { a0[i] = cvtu_tf32(a0[i]); a1[i] = cvtu_tf32(a1[i]); }
            #pragma unroll
            for (int nf = 0; nf < 4; nf++) {
                const int n = wn*32 + nf*8 + g;
                b[nf][0] = __float_as_uint(cvt1_tf32(Bs[k0+tg  ][n]));
                b[nf][1] = __float_as_uint(cvt1_tf32(Bs[k0+tg+4][n]));
            }
            #pragma unroll
            for (int nf = 0; nf < 4; nf++) {
                mma_tf32(acc[0][nf], a0, b[nf]);
                mma_tf32(acc[1][nf], a1, b[nf]);
            }
        }
    }

    // epilogue: RoPE (Q,K), Q scale, tf32 round, store
    const float qscale = 0.088388347648318447f;  // 1/sqrt(128)
    #pragma unroll
    for (int mf = 0; mf < 2; mf++) {
        const int row0 = m0 + wm*32 + mf*16 + g;
        const int row1 = row0 + 8;
        const int t0 = row0 & (T_ - 1);
        const int t1 = row1 & (T_ - 1);
        #pragma unroll
        for (int nf = 0; nf < 4; nf++) {
            const int col = wn*32 + nf*8 + 2*tg;
            const int hi  = col >> 1;
            float re0 = acc[mf][nf][0], im0 = acc[mf][nf][1];
            float re1 = acc[mf][nf][2], im1 = acc[mf][nf][3];
            if (which < 2) {
                float c0 = rc[t0*HALF_ + hi], s0 = rs[t0*HALF_ + hi];
                float c1 = rc[t1*HALF_ + hi], s1 = rs[t1*HALF_ + hi];
                float r2, i2;
                r2 = re0*c0 - im0*s0; i2 = re0*s0 + im0*c0; re0 = r2; im0 = i2;
                r2 = re1*c1 - im1*s1; i2 = re1*s1 + im1*c1; re1 = r2; im1 = i2;
            }
            if (which == 0) { re0 *= qscale; im0 *= qscale; re1 *= qscale; im1 *= qscale; }
            re0 = cvt1_tf32(re0); im0 = cvt1_tf32(im0);
            re1 = cvt1_tf32(re1); im1 = cvt1_tf32(im1);
            *(float2*)&dst[(size_t)row0*HD_ + col] = make_float2(re0, im0);
            *(float2*)&dst[(size_t)row1*HD_ + col] = make_float2(re1, im1);
        }
    }
}

// ---------------------------------------------------------------------------
// Kernel 2: causal flash attention — warp-owns-rows, register softmax.
// (unchanged from R15 — passing at 78.3us)
// ---------------------------------------------------------------------------
#define BQ 32
#define BK 32

struct __align__(16) AttnSmem {
    float Q[BQ][132];
    float K[2][BK][132];
    float V[2][BK][136];
    float P[4][16][36];    // per-warp P patches
};

__global__ __launch_bounds__(128, 2) void attn_kernel(float* __restrict__ out)
{
    extern __shared__ char smem_raw[];
    AttnSmem& sm = *reinterpret_cast<AttnSmem*>(smem_raw);

    // balanced bid -> (qt, b): pairs heavy with light on same SM residue
    const int bid = blockIdx.x;
    int qt, b;
    if (bid < 108)      { qt = bid >> 2;              b = bid & 3; }
    else if (bid < 148) { int j = bid - 108; qt = 27 + (j >> 2); b = j & 3; }
    else                { int j = bid - 148; qt = 63 - (j >> 2); b = j & 3; }

    const int q0   = qt * BQ;
    const int tid  = threadIdx.x;
    const int lane = tid & 31;
    const int w    = tid >> 5;
    const int g    = lane >> 2;
    const int tg   = lane & 3;
    const int wrow = (w & 1) * 16;    // row half
    const int wcol = (w >> 1) * 64;   // O col half

    const float* __restrict__ Qg = g_Q + (size_t)(b*T_)*HD_;
    const float* __restrict__ Kg = g_K + (size_t)(b*T_)*HD_;
    const float* __restrict__ Vg = g_V + (size_t)(b*T_)*HD_;

    // ldmatrix lane address pieces
    const int arow = (lane & 7) + ((lane >> 3) & 1) * 8;
    const int acol = (lane >> 4) * 4;
    const unsigned qAddr = smem_u32(&sm.Q[wrow + arow][acol]);
    const unsigned pAddr = smem_u32(&sm.P[w][arow][acol]);
    const unsigned kBase = smem_u32(&sm.K[0][(lane >> 3)*8 + (lane & 7)][0]);
    const unsigned KBUF  = (unsigned)sizeof(sm.K[0]);   // 32*132*4 bytes

    // prologue: Q + K0 + V0 in one cp.async group
    {
        #pragma unroll
        for (int i = 0; i < 8; i++) {
            int idx = tid + i*128;
            int r = idx >> 5, c4 = idx & 31;
            cp16(smem_u32(&sm.Q[r][c4*4]), Qg + (size_t)(q0 + r)*HD_ + c4*4);
        }
        #pragma unroll
        for (int i = 0; i < 8; i++) {
            int idx = tid + i*128;
            int r = idx >> 5, c4 = idx & 31;
            cp16(smem_u32(&sm.K[0][r][c4*4]), Kg + (size_t)r*HD_ + c4*4);
            cp16(smem_u32(&sm.V[0][r][c4*4]), Vg + (size_t)r*HD_ + c4*4);
        }
        cp_commit();
        cp_wait0();
        __syncthreads();
    }

    // preload Q fragments (iteration-invariant): 16 A-frags = 64 regs
    unsigned qf[16][4];
    #pragma unroll
    for (int ks = 0; ks < 16; ks++)
        ldsm_x4(qf[ks][0], qf[ks][1], qf[ks][2], qf[ks][3], qAddr + ks*32);

    float O[8][4];
    #pragma unroll
    for (int nf = 0; nf < 8; nf++)
        #pragma unroll
        for (int r = 0; r < 4; r++) O[nf][r] = 0.f;
    float m0 = -1e30f, m1 = -1e30f, l0 = 0.f, l1 = 0.f;

    const int qg0 = q0 + wrow + g, qg1 = qg0 + 8;
    const int nk = qt + 1;

    for (int kt = 0; kt < nk; ++kt) {
        const int cur = kt & 1;
        const int k0  = kt * BK;

        if (kt > 0) {
            cp_wait0();        // group for tile kt arrived (prefetched 1 iter ago)
            __syncthreads();   // all warps done with iter kt-1; cp data visible
        }
        // prefetch K/V for kt+1 into the idle buffer
        if (kt + 1 < nk) {
            const int nb = 1 - cur;
            #pragma unroll
            for (int i = 0; i < 8; i++) {
                int idx = tid + i*128;
                int r = idx >> 5, c4 = idx & 31;
                cp16(smem_u32(&sm.K[nb][r][c4*4]),
                     Kg + (size_t)(k0 + BK + r)*HD_ + c4*4);
                cp16(smem_u32(&sm.V[nb][r][c4*4]),
                     Vg + (size_t)(k0 + BK + r)*HD_ + c4*4);
            }
            cp_commit();
        }

        // ---- S = Q K^T : full 16x32 per warp (8 chains of 8) ----
        float sA[4][4], sB[4][4];
        #pragma unroll
        for (int nf = 0; nf < 4; nf++)
            #pragma unroll
            for (int r = 0; r < 4; r++) { sA[nf][r] = 0.f; sB[nf][r] = 0.f; }
        {
            const unsigned ka = kBase + (unsigned)cur * KBUF;
            #pragma unroll
            for (int ks = 0; ks < 8; ks++) {
                unsigned b0[4], b1[4];
                ldsm_x4(b0[0], b0[1], b0[2], b0[3], ka + ks*32);
                ldsm_x4(b1[0], b1[1], b1[2], b1[3], ka + ks*32 + 16);
                #pragma unroll
                for (int nf = 0; nf < 4; nf++) {
                    unsigned bb[2] = { b0[nf], b1[nf] };
                    mma_tf32(sA[nf], qf[ks], bb);
                }
            }
            #pragma unroll
            for (int ks = 8; ks < 16; ks++) {
                unsigned b0[4], b1[4];
                ldsm_x4(b0[0], b0[1], b0[2], b0[3], ka + ks*32);
                ldsm_x4(b1[0], b1[1], b1[2], b1[3], ka + ks*32 + 16);
                #pragma unroll
                for (int nf = 0; nf < 4; nf++) {
                    unsigned bb[2] = { b0[nf], b1[nf] };
                    mma_tf32(sB[nf], qf[ks], bb);
                }
            }
        }

        // ---- mask + register softmax (quad shuffles only) ----
        float s[4][4];
        #pragma unroll
        for (int nf = 0; nf < 4; nf++) {
            const int col = k0 + nf*8 + 2*tg;
            s[nf][0] = (col   <= qg0) ? sA[nf][0]+sB[nf][0] : -1e9f;
            s[nf][1] = (col+1 <= qg0) ? sA[nf][1]+sB[nf][1] : -1e9f;
            s[nf][2] = (col   <= qg1) ? sA[nf][2]+sB[nf][2] : -1e9f;
            s[nf][3] = (col+1 <= qg1) ? sA[nf][3]+sB[nf][3] : -1e9f;
        }
        float mx0 = fmaxf(fmaxf(s[0][0], s[0][1]), fmaxf(s[1][0], s[1][1]));
        mx0 = fmaxf(mx0, fmaxf(fmaxf(s[2][0], s[2][1]), fmaxf(s[3][0], s[3][1])));
        float mx1 = fmaxf(fmaxf(s[0][2], s[0][3]), fmaxf(s[1][2], s[1][3]));
        mx1 = fmaxf(mx1, fmaxf(fmaxf(s[2][2], s[2][3]), fmaxf(s[3][2], s[3][3])));
        #pragma unroll
        for (int o = 1; o < 4; o <<= 1) {
            mx0 = fmaxf(mx0, __shfl_xor_sync(0xffffffffu, mx0, o));
            mx1 = fmaxf(mx1, __shfl_xor_sync(0xffffffffu, mx1, o));
        }
        const float nm0 = fmaxf(m0, mx0), nm1 = fmaxf(m1, mx1);
        const float corr0 = __expf(m0 - nm0), corr1 = __expf(m1 - nm1);
        m0 = nm0; m1 = nm1;

        float p[4][4];
        float sum0 = 0.f, sum1 = 0.f;
        #pragma unroll
        for (int nf = 0; nf < 4; nf++) {
            p[nf][0] = __expf(s[nf][0] - nm0); sum0 += p[nf][0];
            p[nf][1] = __expf(s[nf][1] - nm0); sum0 += p[nf][1];
            p[nf][2] = __expf(s[nf][2] - nm1); sum1 += p[nf][2];
            p[nf][3] = __expf(s[nf][3] - nm1); sum1 += p[nf][3];
        }
        #pragma unroll
        for (int o = 1; o < 4; o <<= 1) {
            sum0 += __shfl_xor_sync(0xffffffffu, sum0, o);
            sum1 += __shfl_xor_sync(0xffffffffu, sum1, o);
        }
        l0 = l0*corr0 + sum0;
        l1 = l1*corr1 + sum1;

        // ---- P -> warp-private smem patch (tf32), then ldmatrix A-frags ----
        #pragma unroll
        for (int nf = 0; nf < 4; nf++) {
            *(float2*)&sm.P[w][g  ][nf*8 + 2*tg] =
                make_float2(cvt1_tf32(p[nf][0]), cvt1_tf32(p[nf][1]));
            *(float2*)&sm.P[w][g+8][nf*8 + 2*tg] =
                make_float2(cvt1_tf32(p[nf][2]), cvt1_tf32(p[nf][3]));
        }
        __syncwarp();
        unsigned pf[4][4];
        #pragma unroll
        for (int ks = 0; ks < 4; ks++)
            ldsm_x4(pf[ks][0], pf[ks][1], pf[ks][2], pf[ks][3], pAddr + ks*32);

        // ---- O = O*corr + P V ----
        #pragma unroll
        for (int nf = 0; nf < 8; nf++) {
            O[nf][0] *= corr0; O[nf][1] *= corr0;
            O[nf][2] *= corr1; O[nf][3] *= corr1;
        }
        {
            const float (*Vs)[136] = sm.V[cur];
            #pragma unroll
            for (int ks = 0; ks < 4; ks++) {
                const int kk = ks*8;
                #pragma unroll
                for (int nf = 0; nf < 8; nf++) {
                    const int n = wcol + nf*8 + g;
                    unsigned bb[2];
                    bb[0] = __float_as_uint(Vs[kk+tg  ][n]);
                    bb[1] = __float_as_uint(Vs[kk+tg+4][n]);
                    mma_tf32(O[nf], pf[ks], bb);
                }
            }
        }
    }

    // ---- final normalize + store ----
    {
        const float inv0 = 1.0f / l0;
        const float inv1 = 1.0f / l1;
        const size_t ro0 = (size_t)(b*T_ + q0 + wrow + g)*HD_;
        const size_t ro1 = ro0 + (size_t)8*HD_;
        #pragma unroll
        for (int nf = 0; nf < 8; nf++) {
            const int col = wcol + nf*8 + 2*tg;
            *(float2*)&out[ro0 + col] = make_float2(O[nf][0]*inv0, O[nf][1]*inv0);
            *(float2*)&out[ro1 + col] = make_float2(O[nf][2]*inv1, O[nf][3]*inv1);
        }
    }
}

// ---------------------------------------------------------------------------
extern "C" void kernel_launch(void* const* d_in, const int* in_sizes, int n_in,
                              void* d_out, int out_size)
{
    const float* x  = (const float*)d_in[0];
    const float* Wq = (const float*)d_in[1];
    const float* Wk = (const float*)d_in[2];
    const float* Wv = (const float*)d_in[3];
    const float* rc = (const float*)d_in[4];
    const float* rs = (const float*)d_in[5];
    // d_in[6] (mask) is exactly the causal -1e9 mask; computed analytically.
    float* out = (float*)d_out;

    cudaFuncSetAttribute(qkv_kernel,
                         cudaFuncAttributeMaxDynamicSharedMemorySize,
                         (int)sizeof(QkvSmem));
    cudaFuncSetAttribute(attn_kernel,
                         cudaFuncAttributeMaxDynamicSharedMemorySize,
                         (int)sizeof(AttnSmem));

    dim3 g1(MTOT/QBM, 3);
    qkv_kernel<<<g1, 256, sizeof(QkvSmem)>>>(x, Wq, Wk, Wv, rc, rs);

    attn_kernel<<<256, 128, sizeof(AttnSmem)>>>(out);
}